// round 15
// baseline (speedup 1.0000x reference)
#include <cuda_runtime.h>
#include <cuda_bf16.h>

// XYLoss: out = (S1 / (B*H*W)) * S2
//   S1 = sum over pixels of [(t0+t1)*softplus(d) - t1*d], d = sigmoid(x1)-sigmoid(x0)
//   S2 = sum(object_mask * box_loss_scale)
// FINAL (champion, frozen): hybrid scheduling — 14 chunks/block STATIC (no
// atomics/barriers) + dynamic tail (3952 chunks) via block-level
// double-buffered counter. Measured at the B300 streaming ceiling
// (6.46 TB/s, DRAM ~81%): 384 MB mandatory reads -> ~63-64 us. All axes
// (occupancy, MLP, burst shape, MUFU count, scheduling) individually swept.

#define HW_   (1024u * 1024u)
#define B_    16u
#define PIX_  (B_ * HW_)        // 16,777,216 pixels
#define NVEC_ (PIX_ / 4u)       // 4,194,304 float4 vectors

constexpr int BLOCKS  = 888;    // 148 SMs * 6 resident blocks = one wave
constexpr int THREADS = 256;
constexpr unsigned CHUNK_VECS   = 256;                    // 1 vec/thread/chunk
constexpr unsigned NCHUNKS      = NVEC_ / CHUNK_VECS;     // 16384
constexpr unsigned STATIC_PER_B = 14;
constexpr unsigned STATIC_TOTAL = STATIC_PER_B * BLOCKS;  // 12432; 3952 dynamic

__device__ float2 g_part[BLOCKS];
__device__ unsigned int g_ticket;   // zero-init; last block wraps it back to 0
__device__ unsigned int g_next;     // dynamic-chunk counter; last block resets to 0

__device__ __forceinline__ float tanh_fast(float x) {
    float r;
    asm("tanh.approx.f32 %0, %1;" : "=f"(r) : "f"(x));   // MUFU.TANH
    return r;
}

__device__ __forceinline__ float per_elem(float x0, float x1, float t0, float t1) {
    float a0 = tanh_fast(0.5f * x0);
    float a1 = tanh_fast(0.5f * x1);
    float d  = 0.5f * (a1 - a0);           // sigmoid(x1)-sigmoid(x0), strictly in (-1,1)
    // softplus(d) = ln2 + d/2 + d^2/8 - d^4/192 + d^6/2880  (|err| <= 2.6e-5 on [-1,1])
    float d2 = d * d;
    float p  = fmaf(d2, 3.472222e-4f, -5.208333e-3f);
    p        = fmaf(d2, p, 0.125f);
    float sp = fmaf(d2, p, fmaf(0.5f, d, 0.69314718f));
    return fmaf(t0 + t1, sp, -t1 * d);
}

__device__ __forceinline__ float4 ldcs4(const float* p) {
    return __ldcs(reinterpret_cast<const float4*>(p));
}

__global__ __launch_bounds__(THREADS, 6) void xyloss_fused(
    const float* __restrict__ mask,
    const float* __restrict__ scale,
    const float* __restrict__ pred,
    const float* __restrict__ truth,
    float* __restrict__ out)
{
    float acc1 = 0.0f;
    float acc2 = 0.0f;

    const int wid = threadIdx.x >> 5;
    const int lid = threadIdx.x & 31;

    __shared__ unsigned s_chunk[2];

    // Prime the FIRST dynamic ticket now; consumed only after the static phase,
    // so its latency is completely hidden and the 888 atomics spread out.
    if (threadIdx.x == 0) s_chunk[0] = STATIC_TOTAL + atomicAdd(&g_next, 1u);

    // ---- Static phase: 14 chunks, zero scheduling overhead ----
    #pragma unroll 2
    for (unsigned i = 0; i < STATIC_PER_B; i++) {
        unsigned chunk = (unsigned)blockIdx.x + i * (unsigned)BLOCKS;
        unsigned v     = chunk * CHUNK_VECS + threadIdx.x;
        unsigned idx   = v << 2;
        unsigned base  = idx + (idx & ~(HW_ - 1u));    // = idx + b*HW_

        float4 m  = ldcs4(mask  + idx);
        float4 sc = ldcs4(scale + idx);
        float4 x0 = ldcs4(pred  + base);
        float4 x1 = ldcs4(pred  + base + HW_);
        float4 t0 = ldcs4(truth + base);
        float4 t1 = ldcs4(truth + base + HW_);

        acc2 += m.x * sc.x + m.y * sc.y + m.z * sc.z + m.w * sc.w;
        acc1 += per_elem(x0.x, x1.x, t0.x, t1.x);
        acc1 += per_elem(x0.y, x1.y, t0.y, t1.y);
        acc1 += per_elem(x0.z, x1.z, t0.z, t1.z);
        acc1 += per_elem(x0.w, x1.w, t0.w, t1.w);
    }

    // ---- Dynamic tail: block-level stealing, double-buffered ticket ----
    __syncthreads();                       // s_chunk[0] now visible to all
    unsigned par   = 0;
    unsigned chunk = s_chunk[0];
    while (chunk < NCHUNKS) {
        if (threadIdx.x == 0) s_chunk[par ^ 1u] = STATIC_TOTAL + atomicAdd(&g_next, 1u);

        unsigned v    = chunk * CHUNK_VECS + threadIdx.x;
        unsigned idx  = v << 2;
        unsigned base = idx + (idx & ~(HW_ - 1u));

        float4 m  = ldcs4(mask  + idx);
        float4 sc = ldcs4(scale + idx);
        float4 x0 = ldcs4(pred  + base);
        float4 x1 = ldcs4(pred  + base + HW_);
        float4 t0 = ldcs4(truth + base);
        float4 t1 = ldcs4(truth + base + HW_);

        acc2 += m.x * sc.x + m.y * sc.y + m.z * sc.z + m.w * sc.w;
        acc1 += per_elem(x0.x, x1.x, t0.x, t1.x);
        acc1 += per_elem(x0.y, x1.y, t0.y, t1.y);
        acc1 += per_elem(x0.z, x1.z, t0.z, t1.z);
        acc1 += per_elem(x0.w, x1.w, t0.w, t1.w);

        __syncthreads();                   // publish prefetched ticket
        par ^= 1u;
        chunk = s_chunk[par];
    }

    // Warp reduce
    #pragma unroll
    for (int off = 16; off > 0; off >>= 1) {
        acc1 += __shfl_xor_sync(0xFFFFFFFFu, acc1, off);
        acc2 += __shfl_xor_sync(0xFFFFFFFFu, acc2, off);
    }

    // Block reduce across 8 warps
    __shared__ float sh1[THREADS / 32];
    __shared__ float sh2[THREADS / 32];
    __shared__ bool  s_last;
    if (lid == 0) { sh1[wid] = acc1; sh2[wid] = acc2; }
    __syncthreads();
    if (threadIdx.x == 0) {
        float b1 = 0.0f, b2 = 0.0f;
        #pragma unroll
        for (int w = 0; w < THREADS / 32; w++) { b1 += sh1[w]; b2 += sh2[w]; }
        g_part[blockIdx.x] = make_float2(b1, b2);
        __threadfence();
        unsigned int t = atomicInc(&g_ticket, BLOCKS - 1);   // wraps to 0 at BLOCKS-1
        s_last = (t == BLOCKS - 1);                          // last arriving block
    }
    __syncthreads();

    if (s_last) {
        if (threadIdx.x == 0) g_next = 0u;   // reset for graph replay
        // Double-precision combine of all BLOCKS partials.
        double a = 0.0, b = 0.0;
        for (int i = threadIdx.x; i < BLOCKS; i += THREADS) {
            float2 p2 = g_part[i];
            a += (double)p2.x;
            b += (double)p2.y;
        }
        #pragma unroll
        for (int off = 16; off > 0; off >>= 1) {
            a += __shfl_xor_sync(0xFFFFFFFFu, a, off);
            b += __shfl_xor_sync(0xFFFFFFFFu, b, off);
        }
        __shared__ double da[THREADS / 32];
        __shared__ double db[THREADS / 32];
        if (lid == 0) { da[wid] = a; db[wid] = b; }
        __syncthreads();
        if (threadIdx.x == 0) {
            double A = 0.0, Bb = 0.0;
            #pragma unroll
            for (int w = 0; w < THREADS / 32; w++) { A += da[w]; Bb += db[w]; }
            double loss = A / (double)PIX_;
            out[0] = (float)(loss * Bb);
        }
    }
}

extern "C" void kernel_launch(void* const* d_in, const int* in_sizes, int n_in,
                              void* d_out, int out_size)
{
    const float* mask  = (const float*)d_in[0];
    const float* scale = (const float*)d_in[1];
    const float* pred  = (const float*)d_in[2];
    const float* truth = (const float*)d_in[3];
    float* out = (float*)d_out;

    xyloss_fused<<<BLOCKS, THREADS>>>(mask, scale, pred, truth, out);
}

// round 16
// speedup vs baseline: 1.0005x; 1.0005x over previous
#include <cuda_runtime.h>
#include <cuda_bf16.h>

// XYLoss: out = (S1 / (B*H*W)) * S2
//   S1 = sum over pixels of [(t0+t1)*softplus(d) - t1*d], d = sigmoid(x1)-sigmoid(x0)
//   S2 = sum(object_mask * box_loss_scale)
// FINAL (champion, frozen): hybrid scheduling — 14 chunks/block STATIC (no
// atomics/barriers) + dynamic tail (3952 chunks) via block-level
// double-buffered counter. At the B300 streaming ceiling (~6.4 TB/s,
// DRAM ~80-82%): 384 MB mandatory reads -> ~64 us. All axes (occupancy,
// MLP, burst shape, MUFU count, scheduling) individually swept; remaining
// deltas are below the ~1 us run-to-run noise floor.

#define HW_   (1024u * 1024u)
#define B_    16u
#define PIX_  (B_ * HW_)        // 16,777,216 pixels
#define NVEC_ (PIX_ / 4u)       // 4,194,304 float4 vectors

constexpr int BLOCKS  = 888;    // 148 SMs * 6 resident blocks = one wave
constexpr int THREADS = 256;
constexpr unsigned CHUNK_VECS   = 256;                    // 1 vec/thread/chunk
constexpr unsigned NCHUNKS      = NVEC_ / CHUNK_VECS;     // 16384
constexpr unsigned STATIC_PER_B = 14;
constexpr unsigned STATIC_TOTAL = STATIC_PER_B * BLOCKS;  // 12432; 3952 dynamic

__device__ float2 g_part[BLOCKS];
__device__ unsigned int g_ticket;   // zero-init; last block wraps it back to 0
__device__ unsigned int g_next;     // dynamic-chunk counter; last block resets to 0

__device__ __forceinline__ float tanh_fast(float x) {
    float r;
    asm("tanh.approx.f32 %0, %1;" : "=f"(r) : "f"(x));   // MUFU.TANH
    return r;
}

__device__ __forceinline__ float per_elem(float x0, float x1, float t0, float t1) {
    float a0 = tanh_fast(0.5f * x0);
    float a1 = tanh_fast(0.5f * x1);
    float d  = 0.5f * (a1 - a0);           // sigmoid(x1)-sigmoid(x0), strictly in (-1,1)
    // softplus(d) = ln2 + d/2 + d^2/8 - d^4/192 + d^6/2880  (|err| <= 2.6e-5 on [-1,1])
    float d2 = d * d;
    float p  = fmaf(d2, 3.472222e-4f, -5.208333e-3f);
    p        = fmaf(d2, p, 0.125f);
    float sp = fmaf(d2, p, fmaf(0.5f, d, 0.69314718f));
    return fmaf(t0 + t1, sp, -t1 * d);
}

__device__ __forceinline__ float4 ldcs4(const float* p) {
    return __ldcs(reinterpret_cast<const float4*>(p));
}

__global__ __launch_bounds__(THREADS, 6) void xyloss_fused(
    const float* __restrict__ mask,
    const float* __restrict__ scale,
    const float* __restrict__ pred,
    const float* __restrict__ truth,
    float* __restrict__ out)
{
    float acc1 = 0.0f;
    float acc2 = 0.0f;

    const int wid = threadIdx.x >> 5;
    const int lid = threadIdx.x & 31;

    __shared__ unsigned s_chunk[2];

    // Prime the FIRST dynamic ticket now; consumed only after the static phase,
    // so its latency is completely hidden and the 888 atomics spread out.
    if (threadIdx.x == 0) s_chunk[0] = STATIC_TOTAL + atomicAdd(&g_next, 1u);

    // ---- Static phase: 14 chunks, zero scheduling overhead ----
    #pragma unroll 2
    for (unsigned i = 0; i < STATIC_PER_B; i++) {
        unsigned chunk = (unsigned)blockIdx.x + i * (unsigned)BLOCKS;
        unsigned v     = chunk * CHUNK_VECS + threadIdx.x;
        unsigned idx   = v << 2;
        unsigned base  = idx + (idx & ~(HW_ - 1u));    // = idx + b*HW_

        float4 m  = ldcs4(mask  + idx);
        float4 sc = ldcs4(scale + idx);
        float4 x0 = ldcs4(pred  + base);
        float4 x1 = ldcs4(pred  + base + HW_);
        float4 t0 = ldcs4(truth + base);
        float4 t1 = ldcs4(truth + base + HW_);

        acc2 += m.x * sc.x + m.y * sc.y + m.z * sc.z + m.w * sc.w;
        acc1 += per_elem(x0.x, x1.x, t0.x, t1.x);
        acc1 += per_elem(x0.y, x1.y, t0.y, t1.y);
        acc1 += per_elem(x0.z, x1.z, t0.z, t1.z);
        acc1 += per_elem(x0.w, x1.w, t0.w, t1.w);
    }

    // ---- Dynamic tail: block-level stealing, double-buffered ticket ----
    __syncthreads();                       // s_chunk[0] now visible to all
    unsigned par   = 0;
    unsigned chunk = s_chunk[0];
    while (chunk < NCHUNKS) {
        if (threadIdx.x == 0) s_chunk[par ^ 1u] = STATIC_TOTAL + atomicAdd(&g_next, 1u);

        unsigned v    = chunk * CHUNK_VECS + threadIdx.x;
        unsigned idx  = v << 2;
        unsigned base = idx + (idx & ~(HW_ - 1u));

        float4 m  = ldcs4(mask  + idx);
        float4 sc = ldcs4(scale + idx);
        float4 x0 = ldcs4(pred  + base);
        float4 x1 = ldcs4(pred  + base + HW_);
        float4 t0 = ldcs4(truth + base);
        float4 t1 = ldcs4(truth + base + HW_);

        acc2 += m.x * sc.x + m.y * sc.y + m.z * sc.z + m.w * sc.w;
        acc1 += per_elem(x0.x, x1.x, t0.x, t1.x);
        acc1 += per_elem(x0.y, x1.y, t0.y, t1.y);
        acc1 += per_elem(x0.z, x1.z, t0.z, t1.z);
        acc1 += per_elem(x0.w, x1.w, t0.w, t1.w);

        __syncthreads();                   // publish prefetched ticket
        par ^= 1u;
        chunk = s_chunk[par];
    }

    // Warp reduce
    #pragma unroll
    for (int off = 16; off > 0; off >>= 1) {
        acc1 += __shfl_xor_sync(0xFFFFFFFFu, acc1, off);
        acc2 += __shfl_xor_sync(0xFFFFFFFFu, acc2, off);
    }

    // Block reduce across 8 warps
    __shared__ float sh1[THREADS / 32];
    __shared__ float sh2[THREADS / 32];
    __shared__ bool  s_last;
    if (lid == 0) { sh1[wid] = acc1; sh2[wid] = acc2; }
    __syncthreads();
    if (threadIdx.x == 0) {
        float b1 = 0.0f, b2 = 0.0f;
        #pragma unroll
        for (int w = 0; w < THREADS / 32; w++) { b1 += sh1[w]; b2 += sh2[w]; }
        g_part[blockIdx.x] = make_float2(b1, b2);
        __threadfence();
        unsigned int t = atomicInc(&g_ticket, BLOCKS - 1);   // wraps to 0 at BLOCKS-1
        s_last = (t == BLOCKS - 1);                          // last arriving block
    }
    __syncthreads();

    if (s_last) {
        if (threadIdx.x == 0) g_next = 0u;   // reset for graph replay
        // Double-precision combine of all BLOCKS partials.
        double a = 0.0, b = 0.0;
        for (int i = threadIdx.x; i < BLOCKS; i += THREADS) {
            float2 p2 = g_part[i];
            a += (double)p2.x;
            b += (double)p2.y;
        }
        #pragma unroll
        for (int off = 16; off > 0; off >>= 1) {
            a += __shfl_xor_sync(0xFFFFFFFFu, a, off);
            b += __shfl_xor_sync(0xFFFFFFFFu, b, off);
        }
        __shared__ double da[THREADS / 32];
        __shared__ double db[THREADS / 32];
        if (lid == 0) { da[wid] = a; db[wid] = b; }
        __syncthreads();
        if (threadIdx.x == 0) {
            double A = 0.0, Bb = 0.0;
            #pragma unroll
            for (int w = 0; w < THREADS / 32; w++) { A += da[w]; Bb += db[w]; }
            double loss = A / (double)PIX_;
            out[0] = (float)(loss * Bb);
        }
    }
}

extern "C" void kernel_launch(void* const* d_in, const int* in_sizes, int n_in,
                              void* d_out, int out_size)
{
    const float* mask  = (const float*)d_in[0];
    const float* scale = (const float*)d_in[1];
    const float* pred  = (const float*)d_in[2];
    const float* truth = (const float*)d_in[3];
    float* out = (float*)d_out;

    xyloss_fused<<<BLOCKS, THREADS>>>(mask, scale, pred, truth, out);
}

// round 17
// speedup vs baseline: 1.0045x; 1.0040x over previous
#include <cuda_runtime.h>
#include <cuda_bf16.h>

// XYLoss: out = (S1 / (B*H*W)) * S2
//   S1 = sum over pixels of [(t0+t1)*softplus(d) - t1*d], d = sigmoid(x1)-sigmoid(x0)
//   S2 = sum(object_mask * box_loss_scale)
// Hybrid scheduling with 512-vec chunks (2 vecs/thread): 7 static chunks/block
// + dynamic tail 1976 chunks (~2.2/block). Same work split and balance slack
// as the 64.0us champion, but HALF the dynamic-phase atomics + barriers, and
// every dynamic iteration carries a 12-load front batch.

#define HW_   (1024u * 1024u)
#define B_    16u
#define PIX_  (B_ * HW_)        // 16,777,216 pixels
#define NVEC_ (PIX_ / 4u)       // 4,194,304 float4 vectors

constexpr int BLOCKS  = 888;    // 148 SMs * 6 resident blocks = one wave
constexpr int THREADS = 256;
constexpr unsigned CHUNK_VECS   = 512;                    // 2 vecs/thread/chunk
constexpr unsigned NCHUNKS      = NVEC_ / CHUNK_VECS;     // 8192
constexpr unsigned STATIC_PER_B = 7;                      // = 14 old-chunks of work
constexpr unsigned STATIC_TOTAL = STATIC_PER_B * BLOCKS;  // 6216; 1976 dynamic

__device__ float2 g_part[BLOCKS];
__device__ unsigned int g_ticket;   // zero-init; last block wraps it back to 0
__device__ unsigned int g_next;     // dynamic-chunk counter; last block resets to 0

__device__ __forceinline__ float tanh_fast(float x) {
    float r;
    asm("tanh.approx.f32 %0, %1;" : "=f"(r) : "f"(x));   // MUFU.TANH
    return r;
}

__device__ __forceinline__ float per_elem(float x0, float x1, float t0, float t1) {
    float a0 = tanh_fast(0.5f * x0);
    float a1 = tanh_fast(0.5f * x1);
    float d  = 0.5f * (a1 - a0);           // sigmoid(x1)-sigmoid(x0), strictly in (-1,1)
    // softplus(d) = ln2 + d/2 + d^2/8 - d^4/192 + d^6/2880  (|err| <= 2.6e-5 on [-1,1])
    float d2 = d * d;
    float p  = fmaf(d2, 3.472222e-4f, -5.208333e-3f);
    p        = fmaf(d2, p, 0.125f);
    float sp = fmaf(d2, p, fmaf(0.5f, d, 0.69314718f));
    return fmaf(t0 + t1, sp, -t1 * d);
}

__device__ __forceinline__ float4 ldcs4(const float* p) {
    return __ldcs(reinterpret_cast<const float4*>(p));
}

// Process one 512-vec chunk: thread handles vec (chunk*512 + tid) and (+256).
__device__ __forceinline__ void do_chunk(
    unsigned chunk,
    const float* __restrict__ mask,  const float* __restrict__ scale,
    const float* __restrict__ pred,  const float* __restrict__ truth,
    float& acc1, float& acc2)
{
    unsigned vbase = chunk * CHUNK_VECS + threadIdx.x;
    #pragma unroll
    for (unsigned sub = 0; sub < 2; sub++) {
        unsigned v    = vbase + sub * 256u;
        unsigned idx  = v << 2;                       // pixel index (multiple of 4)
        unsigned base = idx + (idx & ~(HW_ - 1u));    // = idx + b*HW_

        float4 m  = ldcs4(mask  + idx);
        float4 sc = ldcs4(scale + idx);
        float4 x0 = ldcs4(pred  + base);
        float4 x1 = ldcs4(pred  + base + HW_);
        float4 t0 = ldcs4(truth + base);
        float4 t1 = ldcs4(truth + base + HW_);

        acc2 += m.x * sc.x + m.y * sc.y + m.z * sc.z + m.w * sc.w;
        acc1 += per_elem(x0.x, x1.x, t0.x, t1.x);
        acc1 += per_elem(x0.y, x1.y, t0.y, t1.y);
        acc1 += per_elem(x0.z, x1.z, t0.z, t1.z);
        acc1 += per_elem(x0.w, x1.w, t0.w, t1.w);
    }
}

__global__ __launch_bounds__(THREADS, 6) void xyloss_fused(
    const float* __restrict__ mask,
    const float* __restrict__ scale,
    const float* __restrict__ pred,
    const float* __restrict__ truth,
    float* __restrict__ out)
{
    float acc1 = 0.0f;
    float acc2 = 0.0f;

    const int wid = threadIdx.x >> 5;
    const int lid = threadIdx.x & 31;

    __shared__ unsigned s_chunk[2];

    // Prime the FIRST dynamic ticket now; consumed only after the static phase,
    // so its latency is completely hidden and the 888 atomics spread out.
    if (threadIdx.x == 0) s_chunk[0] = STATIC_TOTAL + atomicAdd(&g_next, 1u);

    // ---- Static phase: 7 chunks (= 14 old), zero scheduling overhead ----
    for (unsigned i = 0; i < STATIC_PER_B; i++) {
        unsigned chunk = (unsigned)blockIdx.x + i * (unsigned)BLOCKS;
        do_chunk(chunk, mask, scale, pred, truth, acc1, acc2);
    }

    // ---- Dynamic tail: block-level stealing, double-buffered ticket ----
    __syncthreads();                       // s_chunk[0] now visible to all
    unsigned par   = 0;
    unsigned chunk = s_chunk[0];
    while (chunk < NCHUNKS) {
        if (threadIdx.x == 0) s_chunk[par ^ 1u] = STATIC_TOTAL + atomicAdd(&g_next, 1u);

        do_chunk(chunk, mask, scale, pred, truth, acc1, acc2);

        __syncthreads();                   // publish prefetched ticket
        par ^= 1u;
        chunk = s_chunk[par];
    }

    // Warp reduce
    #pragma unroll
    for (int off = 16; off > 0; off >>= 1) {
        acc1 += __shfl_xor_sync(0xFFFFFFFFu, acc1, off);
        acc2 += __shfl_xor_sync(0xFFFFFFFFu, acc2, off);
    }

    // Block reduce across 8 warps
    __shared__ float sh1[THREADS / 32];
    __shared__ float sh2[THREADS / 32];
    __shared__ bool  s_last;
    if (lid == 0) { sh1[wid] = acc1; sh2[wid] = acc2; }
    __syncthreads();
    if (threadIdx.x == 0) {
        float b1 = 0.0f, b2 = 0.0f;
        #pragma unroll
        for (int w = 0; w < THREADS / 32; w++) { b1 += sh1[w]; b2 += sh2[w]; }
        g_part[blockIdx.x] = make_float2(b1, b2);
        __threadfence();
        unsigned int t = atomicInc(&g_ticket, BLOCKS - 1);   // wraps to 0 at BLOCKS-1
        s_last = (t == BLOCKS - 1);                          // last arriving block
    }
    __syncthreads();

    if (s_last) {
        if (threadIdx.x == 0) g_next = 0u;   // reset for graph replay
        // Double-precision combine of all BLOCKS partials.
        double a = 0.0, b = 0.0;
        for (int i = threadIdx.x; i < BLOCKS; i += THREADS) {
            float2 p2 = g_part[i];
            a += (double)p2.x;
            b += (double)p2.y;
        }
        #pragma unroll
        for (int off = 16; off > 0; off >>= 1) {
            a += __shfl_xor_sync(0xFFFFFFFFu, a, off);
            b += __shfl_xor_sync(0xFFFFFFFFu, b, off);
        }
        __shared__ double da[THREADS / 32];
        __shared__ double db[THREADS / 32];
        if (lid == 0) { da[wid] = a; db[wid] = b; }
        __syncthreads();
        if (threadIdx.x == 0) {
            double A = 0.0, Bb = 0.0;
            #pragma unroll
            for (int w = 0; w < THREADS / 32; w++) { A += da[w]; Bb += db[w]; }
            double loss = A / (double)PIX_;
            out[0] = (float)(loss * Bb);
        }
    }
}

extern "C" void kernel_launch(void* const* d_in, const int* in_sizes, int n_in,
                              void* d_out, int out_size)
{
    const float* mask  = (const float*)d_in[0];
    const float* scale = (const float*)d_in[1];
    const float* pred  = (const float*)d_in[2];
    const float* truth = (const float*)d_in[3];
    float* out = (float*)d_out;

    xyloss_fused<<<BLOCKS, THREADS>>>(mask, scale, pred, truth, out);
}